// round 2
// baseline (speedup 1.0000x reference)
#include <cuda_runtime.h>
#include <math.h>

#define BATCH 256
#define SEQ   256
#define NIN   512
#define HID   1024
#define MOUT  512

// Ping-pong recurrent state (sanctioned __device__ scratch; no allocations).
__device__ float g_h0[BATCH * HID];
__device__ float g_h1[BATCH * HID];
__device__ float g_c0[BATCH * HID];
__device__ float g_c1[BATCH * HID];

__device__ __forceinline__ float sigmoidf(float v) {
    return 1.0f / (1.0f + __expf(-v));
}

__global__ void init_state() {
    int i = blockIdx.x * blockDim.x + threadIdx.x;
    if (i < BATCH * HID) {
        g_h0[i] = 0.0f;
        g_c0[i] = 0.0f;
    }
}

// One recurrent timestep, gate-fused:
//   z[b, g*H + j] = sum_c h[b,c]*Wh_g[j,c] + sum_n x[b,t,n]*Wx_g[j,n] + b_g[j]
//   c' = tanh(zg)*sig(zi) + c*sig(zf);  h' = tanh(c')*sig(zo)
// Block tile: 64 batch rows x 32 hidden cols x 4 gates. Grid (4, 32) = 128 blocks.
// 256 threads; per-thread micro-tile 4b x 2j x 4 gates = 32 accumulators.
// K = 1536 (first 1024 from h/Wh, last 512 from x_t/Wx).
__global__ __launch_bounds__(256) void lstm_step(
    const float* __restrict__ x, int t,
    const float* __restrict__ Wh0, const float* __restrict__ Wh1,
    const float* __restrict__ Wh2, const float* __restrict__ Wh3,
    const float* __restrict__ Wx0, const float* __restrict__ Wx1,
    const float* __restrict__ Wx2, const float* __restrict__ Wx3,
    const float* __restrict__ bv0, const float* __restrict__ bv1,
    const float* __restrict__ bv2, const float* __restrict__ bv3)
{
    const float* h_in  = (t & 1) ? g_h1 : g_h0;
    const float* c_in  = (t & 1) ? g_c1 : g_c0;
    float*       h_out = (t & 1) ? g_h0 : g_h1;
    float*       c_out = (t & 1) ? g_c0 : g_c1;

    // A tile: 32(k) x 64(b), row stride 68 floats (=272 B, 16B-aligned rows).
    // B tiles: per gate 32(k) x 32(j), row stride 34 (8B-aligned for float2).
    __shared__ __align__(16) float As[32][68];
    __shared__ __align__(16) float Bs[4][32][34];

    const int tid = threadIdx.x;
    const int m0  = blockIdx.x * 64;   // batch tile base
    const int j0  = blockIdx.y * 32;   // hidden-col tile base
    const int cl  = tid & 31;          // k-lane within tile
    const int rw  = tid >> 5;          // 0..7

    float acc[4][4][2];
#pragma unroll
    for (int g = 0; g < 4; g++)
#pragma unroll
        for (int u = 0; u < 4; u++) {
            acc[g][u][0] = 0.0f;
            acc[g][u][1] = 0.0f;
        }

    const float* Whp[4] = {Wh0, Wh1, Wh2, Wh3};
    const float* Wxp[4] = {Wx0, Wx1, Wx2, Wx3};

    for (int k0 = 0; k0 < HID + NIN; k0 += 32) {
        if (k0 < HID) {
            // A from h_in, B from Wh_g (coalesced along K, transposed into smem)
#pragma unroll
            for (int i = 0; i < 8; i++)
                As[cl][rw + i * 8] = h_in[(m0 + rw + i * 8) * HID + k0 + cl];
#pragma unroll
            for (int g = 0; g < 4; g++)
#pragma unroll
                for (int i = 0; i < 4; i++)
                    Bs[g][cl][rw + i * 8] =
                        Whp[g][(j0 + rw + i * 8) * HID + k0 + cl];
        } else {
            const int kk = k0 - HID;
#pragma unroll
            for (int i = 0; i < 8; i++)
                As[cl][rw + i * 8] =
                    x[((size_t)(m0 + rw + i * 8) * SEQ + t) * NIN + kk + cl];
#pragma unroll
            for (int g = 0; g < 4; g++)
#pragma unroll
                for (int i = 0; i < 4; i++)
                    Bs[g][cl][rw + i * 8] =
                        Wxp[g][(j0 + rw + i * 8) * NIN + kk + cl];
        }
        __syncthreads();

        const int bb = (tid >> 4) << 2;   // 0..60, batch offset in tile
        const int jj = (tid & 15) << 1;   // 0..30, col offset in tile
#pragma unroll
        for (int k = 0; k < 32; k++) {
            float4 a = *reinterpret_cast<const float4*>(&As[k][bb]);
#pragma unroll
            for (int g = 0; g < 4; g++) {
                float2 w = *reinterpret_cast<const float2*>(&Bs[g][k][jj]);
                acc[g][0][0] += a.x * w.x;  acc[g][0][1] += a.x * w.y;
                acc[g][1][0] += a.y * w.x;  acc[g][1][1] += a.y * w.y;
                acc[g][2][0] += a.z * w.x;  acc[g][2][1] += a.z * w.y;
                acc[g][3][0] += a.w * w.x;  acc[g][3][1] += a.w * w.y;
            }
        }
        __syncthreads();
    }

    // Epilogue: gates + state update, all in-register.
    const int bb = (tid >> 4) << 2;
    const int jj = (tid & 15) << 1;
#pragma unroll
    for (int ji = 0; ji < 2; ji++) {
        const int j  = j0 + jj + ji;
        const float bg = bv0[j];
        const float bi = bv1[j];
        const float bf = bv2[j];
        const float bo = bv3[j];
#pragma unroll
        for (int u = 0; u < 4; u++) {
            const int b  = m0 + bb + u;
            const float zg = acc[0][u][ji] + bg;
            const float zi = acc[1][u][ji] + bi;
            const float zf = acc[2][u][ji] + bf;
            const float zo = acc[3][u][ji] + bo;
            const float cp = c_in[b * HID + j];
            const float cn = tanhf(zg) * sigmoidf(zi) + cp * sigmoidf(zf);
            const float hn = tanhf(cn) * sigmoidf(zo);
            c_out[b * HID + j] = cn;
            h_out[b * HID + j] = hn;
        }
    }
}

// Final projection: out[b,m] = sum_j h[b,j] * Wp[m,j] + bp[m]
// Block tile 64x64, 256 threads, per-thread 4x4, K=1024. Grid (4, 8).
__global__ __launch_bounds__(256) void proj_kernel(
    const float* __restrict__ Wp, const float* __restrict__ bp,
    float* __restrict__ out)
{
    const float* h = g_h0;   // after 256 steps the live state is buffer 0

    __shared__ __align__(16) float As[32][68];
    __shared__ __align__(16) float Bn[32][68];

    const int tid = threadIdx.x;
    const int m0  = blockIdx.x * 64;   // batch
    const int n0  = blockIdx.y * 64;   // output col
    const int cl  = tid & 31;
    const int rw  = tid >> 5;

    float acc[4][4];
#pragma unroll
    for (int u = 0; u < 4; u++)
#pragma unroll
        for (int v = 0; v < 4; v++) acc[u][v] = 0.0f;

    for (int k0 = 0; k0 < HID; k0 += 32) {
#pragma unroll
        for (int i = 0; i < 8; i++) {
            As[cl][rw + i * 8] = h[(m0 + rw + i * 8) * HID + k0 + cl];
            Bn[cl][rw + i * 8] = Wp[(n0 + rw + i * 8) * HID + k0 + cl];
        }
        __syncthreads();

        const int bbv = (tid >> 4) << 2;
        const int nnv = (tid & 15) << 2;
#pragma unroll
        for (int k = 0; k < 32; k++) {
            float4 a = *reinterpret_cast<const float4*>(&As[k][bbv]);
            float4 w = *reinterpret_cast<const float4*>(&Bn[k][nnv]);
            float av[4] = {a.x, a.y, a.z, a.w};
            float wv[4] = {w.x, w.y, w.z, w.w};
#pragma unroll
            for (int u = 0; u < 4; u++)
#pragma unroll
                for (int v = 0; v < 4; v++)
                    acc[u][v] += av[u] * wv[v];
        }
        __syncthreads();
    }

    const int bbv = (tid >> 4) << 2;
    const int nnv = (tid & 15) << 2;
#pragma unroll
    for (int u = 0; u < 4; u++)
#pragma unroll
        for (int v = 0; v < 4; v++)
            out[(m0 + bbv + u) * MOUT + n0 + nnv + v] =
                acc[u][v] + bp[n0 + nnv + v];
}

extern "C" void kernel_launch(void* const* d_in, const int* in_sizes, int n_in,
                              void* d_out, int out_size) {
    (void)in_sizes; (void)n_in; (void)out_size;
    const float* x   = (const float*)d_in[0];
    const float* Wgx = (const float*)d_in[1];
    const float* bg  = (const float*)d_in[2];
    const float* Wgh = (const float*)d_in[3];
    const float* Wix = (const float*)d_in[4];
    const float* bi  = (const float*)d_in[5];
    const float* Wih = (const float*)d_in[6];
    const float* Wfx = (const float*)d_in[7];
    const float* bf  = (const float*)d_in[8];
    const float* Wfh = (const float*)d_in[9];
    const float* Wox = (const float*)d_in[10];
    const float* bo  = (const float*)d_in[11];
    const float* Woh = (const float*)d_in[12];
    const float* Wp  = (const float*)d_in[13];
    const float* bp  = (const float*)d_in[14];
    float* out = (float*)d_out;

    init_state<<<(BATCH * HID + 255) / 256, 256>>>();

    dim3 sgrid(BATCH / 64, HID / 32);
    for (int t = 0; t < SEQ; t++) {
        lstm_step<<<sgrid, 256>>>(x, t,
                                  Wgh, Wih, Wfh, Woh,
                                  Wgx, Wix, Wfx, Wox,
                                  bg, bi, bf, bo);
    }

    proj_kernel<<<dim3(BATCH / 64, MOUT / 64), 256>>>(Wp, bp, out);
}

// round 5
// speedup vs baseline: 3.4907x; 3.4907x over previous
#include <cuda_runtime.h>
#include <cuda_bf16.h>
#include <math.h>
#include <stdint.h>

#define BATCH 256
#define SEQ   256
#define NIN   512
#define HID   1024
#define MOUT  512
#define GDIM  4096            // 4*HID packed gate columns (p = 4j + gate)
#define KTOT  1536            // HID + NIN
#define KC    64              // K per chunk (64 bf16 = 128B rows)
#define NCHUNK (KTOT / KC)    // 24

#define TM 64
#define TN 128
// per-stage tiles: A_hi 8K | A_lo 8K | B_hi 16K | B_lo 16K
#define A_LO_OFF  8192
#define B_HI_OFF 16384
#define B_LO_OFF 32768
#define STAGE_BYTES 49152
#define SMEM_DYN (1024 + 2 * STAGE_BYTES)   // 1KB slack for 1024B tile alignment

// ---------------- device scratch (static; no allocations) ----------------
__device__ __align__(256) float          g_c[2][BATCH * HID];
__device__ __align__(256) __nv_bfloat16  g_hhi[2][BATCH * HID];
__device__ __align__(256) __nv_bfloat16  g_hlo[2][BATCH * HID];
__device__ __align__(256) float          g_hf[BATCH * HID];
__device__ __align__(256) __nv_bfloat16  g_wphi[GDIM * KTOT];
__device__ __align__(256) __nv_bfloat16  g_wplo[GDIM * KTOT];
__device__ __align__(256) float          g_bpack[GDIM];
__device__ __align__(256) __nv_bfloat16  g_xhi[BATCH * SEQ * NIN];
__device__ __align__(256) __nv_bfloat16  g_xlo[BATCH * SEQ * NIN];

// ---------------- helpers ----------------
__device__ __forceinline__ uint32_t smem_u32(const void* p) {
    uint32_t a;
    asm("{ .reg .u64 t; cvta.to.shared.u64 t, %1; cvt.u32.u64 %0, t; }" : "=r"(a) : "l"(p));
    return a;
}
__device__ __forceinline__ uint32_t swz128(uint32_t off) {
    return off ^ ((off >> 3) & 0x70);
}
__device__ __forceinline__ void cp16(uint32_t dst, const void* src) {
    asm volatile("cp.async.cg.shared.global [%0], [%1], 16;" :: "r"(dst), "l"(src) : "memory");
}
#define CP_COMMIT() asm volatile("cp.async.commit_group;" ::: "memory")
#define CP_WAIT(n)  asm volatile("cp.async.wait_group %0;" :: "n"(n) : "memory")

#define LDSM4(r, addr) \
    asm volatile("ldmatrix.sync.aligned.m8n8.x4.shared.b16 {%0,%1,%2,%3}, [%4];" \
        : "=r"((r)[0]), "=r"((r)[1]), "=r"((r)[2]), "=r"((r)[3]) : "r"(addr))

#define MMA16816(c, a, b) \
    asm volatile("mma.sync.aligned.m16n8k16.row.col.f32.bf16.bf16.f32 " \
        "{%0,%1,%2,%3}, {%4,%5,%6,%7}, {%8,%9}, {%0,%1,%2,%3};" \
        : "+f"((c)[0]), "+f"((c)[1]), "+f"((c)[2]), "+f"((c)[3]) \
        : "r"((a)[0]), "r"((a)[1]), "r"((a)[2]), "r"((a)[3]), \
          "r"((b)[0]), "r"((b)[1]))

__device__ __forceinline__ float sigmoidf_(float v) {
    return 1.0f / (1.0f + __expf(-v));
}

// ---------------- prologue kernels ----------------
__global__ void init_state() {
    int i = blockIdx.x * blockDim.x + threadIdx.x;
    if (i < BATCH * HID) {
        g_c[0][i] = 0.0f;
        g_hhi[0][i] = __float2bfloat16(0.0f);
        g_hlo[0][i] = __float2bfloat16(0.0f);
    }
}

__global__ void split_x(const float* __restrict__ x) {
    int i = blockIdx.x * blockDim.x + threadIdx.x;
    if (i < BATCH * SEQ * NIN) {
        float v = x[i];
        __nv_bfloat16 hi = __float2bfloat16(v);
        g_xhi[i] = hi;
        g_xlo[i] = __float2bfloat16(v - __bfloat162float(hi));
    }
}

__global__ void pack_w(const float* __restrict__ Wgh, const float* __restrict__ Wih,
                       const float* __restrict__ Wfh, const float* __restrict__ Woh,
                       const float* __restrict__ Wgx, const float* __restrict__ Wix,
                       const float* __restrict__ Wfx, const float* __restrict__ Wox) {
    const float* Wh[4] = {Wgh, Wih, Wfh, Woh};
    const float* Wx[4] = {Wgx, Wix, Wfx, Wox};
    long i = (long)blockIdx.x * blockDim.x + threadIdx.x;
    if (i < (long)GDIM * KTOT) {
        int p = (int)(i / KTOT);
        int k = (int)(i % KTOT);
        int j = p >> 2, g = p & 3;
        float v = (k < HID) ? Wh[g][j * HID + k] : Wx[g][j * NIN + (k - HID)];
        __nv_bfloat16 hi = __float2bfloat16(v);
        g_wphi[i] = hi;
        g_wplo[i] = __float2bfloat16(v - __bfloat162float(hi));
    }
}

__global__ void pack_b(const float* __restrict__ bg, const float* __restrict__ bi,
                       const float* __restrict__ bf, const float* __restrict__ bo) {
    const float* bv[4] = {bg, bi, bf, bo};
    int p = blockIdx.x * blockDim.x + threadIdx.x;
    if (p < GDIM) g_bpack[p] = bv[p & 3][p >> 2];
}

// ---------------- mma.sync recurrent step ----------------
// Grid (4, 32); CTA tile 64 batch x 128 packed gate cols; K = 1536.
// Split-bf16: C += Ah*Bh + Ah*Bl + Al*Bh (fp32 accum in registers).
__device__ __forceinline__ void issue_loads(
    int ck, int stage, int t, int tid, int m0, int p0,
    uint32_t tiles, const __nv_bfloat16* hhi_in, const __nv_bfloat16* hlo_in)
{
    const int k0 = ck * KC;
    const uint32_t sb = tiles + stage * STAGE_BYTES;
    // A: 64 rows x 8 16B-groups, hi + lo
#pragma unroll
    for (int c = 0; c < 2; c++) {
        int id = tid + c * 256;          // 0..511
        int r = id >> 3, c8 = id & 7;
        uint32_t off = swz128((uint32_t)(r * 128 + c8 * 16));
        int row = m0 + r;
        const __nv_bfloat16 *ghi, *glo;
        if (k0 < HID) {
            ghi = &hhi_in[row * HID + k0 + c8 * 8];
            glo = &hlo_in[row * HID + k0 + c8 * 8];
        } else {
            size_t xo = ((size_t)row * SEQ + t) * NIN + (k0 - HID) + c8 * 8;
            ghi = &g_xhi[xo];
            glo = &g_xlo[xo];
        }
        cp16(sb + off, ghi);
        cp16(sb + A_LO_OFF + off, glo);
    }
    // B: 128 rows x 8 16B-groups, hi + lo
#pragma unroll
    for (int c = 0; c < 4; c++) {
        int id = tid + c * 256;          // 0..1023
        int r = id >> 3, c8 = id & 7;
        uint32_t off = swz128((uint32_t)(r * 128 + c8 * 16));
        size_t wo = (size_t)(p0 + r) * KTOT + k0 + c8 * 8;
        cp16(sb + B_HI_OFF + off, &g_wphi[wo]);
        cp16(sb + B_LO_OFF + off, &g_wplo[wo]);
    }
    CP_COMMIT();
}

__global__ __launch_bounds__(256, 1) void lstm_step_mma(int t) {
    extern __shared__ __align__(1024) char smem[];
    const uint32_t sbase = smem_u32(smem);
    const uint32_t tiles = (sbase + 1023u) & ~1023u;   // 1024B-aligned tile region

    const int tid = threadIdx.x;
    const int lane = tid & 31;
    const int wid = tid >> 5;
    const int wm = wid >> 2;    // 0..1  (M)
    const int wn = wid & 3;     // 0..3  (N)
    const int m0 = blockIdx.x * TM;
    const int p0 = blockIdx.y * TN;

    const int pin = t & 1, pout = pin ^ 1;
    const __nv_bfloat16* hhi_in = g_hhi[pin];
    const __nv_bfloat16* hlo_in = g_hlo[pin];
    const float* c_in = g_c[pin];
    float* c_out = g_c[pout];
    __nv_bfloat16* hhi_out = g_hhi[pout];
    __nv_bfloat16* hlo_out = g_hlo[pout];

    // Per-lane unswizzled base offsets for ldmatrix addresses.
    const int mat = lane >> 3;
    uint32_t aBaseOff[2], bBaseOff[2];
#pragma unroll
    for (int mt = 0; mt < 2; mt++) {
        int rowA = wm * 32 + mt * 16 + (lane & 7) + (mat & 1) * 8;
        aBaseOff[mt] = (uint32_t)(rowA * 128 + ((lane >> 4) & 1) * 16);
    }
#pragma unroll
    for (int q = 0; q < 2; q++) {
        int rowB = wn * 32 + q * 16 + (mat >> 1) * 8 + (lane & 7);
        bBaseOff[q] = (uint32_t)(rowB * 128 + (mat & 1) * 16);
    }

    float acc[2][4][4];
#pragma unroll
    for (int mt = 0; mt < 2; mt++)
#pragma unroll
        for (int nt = 0; nt < 4; nt++)
#pragma unroll
            for (int e = 0; e < 4; e++) acc[mt][nt][e] = 0.0f;

    issue_loads(0, 0, t, tid, m0, p0, tiles, hhi_in, hlo_in);

    for (int i = 0; i < NCHUNK; i++) {
        const int st = i & 1;
        if (i + 1 < NCHUNK) {
            issue_loads(i + 1, st ^ 1, t, tid, m0, p0, tiles, hhi_in, hlo_in);
            CP_WAIT(1);
        } else {
            CP_WAIT(0);
        }
        __syncthreads();   // chunk i visible to all warps

        const uint32_t sb = tiles + st * STAGE_BYTES;
#pragma unroll
        for (int pass = 0; pass < 3; pass++) {
            const uint32_t aB = sb + (pass == 2 ? A_LO_OFF : 0);
            const uint32_t bB = sb + (pass == 1 ? B_LO_OFF : B_HI_OFF);
#pragma unroll
            for (int ks = 0; ks < 4; ks++) {
                uint32_t a[2][4];
#pragma unroll
                for (int mt = 0; mt < 2; mt++)
                    LDSM4(a[mt], aB + swz128(aBaseOff[mt] + ks * 32));
                uint32_t b[4][2];
#pragma unroll
                for (int q = 0; q < 2; q++) {
                    uint32_t r4[4];
                    LDSM4(r4, bB + swz128(bBaseOff[q] + ks * 32));
                    b[2 * q][0] = r4[0]; b[2 * q][1] = r4[1];
                    b[2 * q + 1][0] = r4[2]; b[2 * q + 1][1] = r4[3];
                }
#pragma unroll
                for (int mt = 0; mt < 2; mt++)
#pragma unroll
                    for (int nt = 0; nt < 4; nt++)
                        MMA16816(acc[mt][nt], a[mt], b[nt]);
            }
        }
        __syncthreads();   // stage st free for overwrite next iteration
    }

    // ---- epilogue: exchange z via smem (reuse stage 0), then gate math ----
    float* zs = (float*)(smem + (tiles - sbase));     // 64 x 132 fp32 = 33792 B
#pragma unroll
    for (int mt = 0; mt < 2; mt++)
#pragma unroll
        for (int nt = 0; nt < 4; nt++) {
            int r = wm * 32 + mt * 16 + (lane >> 2);
            int cc = wn * 32 + nt * 8 + (lane & 3) * 2;
            zs[r * 132 + cc]           = acc[mt][nt][0];
            zs[r * 132 + cc + 1]       = acc[mt][nt][1];
            zs[(r + 8) * 132 + cc]     = acc[mt][nt][2];
            zs[(r + 8) * 132 + cc + 1] = acc[mt][nt][3];
        }
    __syncthreads();

#pragma unroll
    for (int e = 0; e < 8; e++) {
        int idx = tid + e * 256;          // 0..2047
        int r = idx >> 5;                 // 0..63
        int jj = idx & 31;                // 0..31
        int b = m0 + r;
        int j = (p0 >> 2) + jj;
        float4 z = *reinterpret_cast<const float4*>(&zs[r * 132 + jj * 4]);
        float4 bb = *reinterpret_cast<const float4*>(&g_bpack[p0 + jj * 4]);
        float zg = z.x + bb.x;
        float zi = z.y + bb.y;
        float zf = z.z + bb.z;
        float zo = z.w + bb.w;
        float cp = c_in[b * HID + j];
        float cn = tanhf(zg) * sigmoidf_(zi) + cp * sigmoidf_(zf);
        float hn = tanhf(cn) * sigmoidf_(zo);
        c_out[b * HID + j] = cn;
        g_hf[b * HID + j] = hn;
        __nv_bfloat16 hi = __float2bfloat16(hn);
        hhi_out[b * HID + j] = hi;
        hlo_out[b * HID + j] = __float2bfloat16(hn - __bfloat162float(hi));
    }
}

// ---------------- final projection (SIMT fp32) ----------------
__global__ __launch_bounds__(256) void proj_kernel(
    const float* __restrict__ Wp, const float* __restrict__ bp,
    float* __restrict__ out)
{
    const float* h = g_hf;
    __shared__ __align__(16) float As[32][68];
    __shared__ __align__(16) float Bn[32][68];

    const int tid = threadIdx.x;
    const int m0 = blockIdx.x * 64;
    const int n0 = blockIdx.y * 64;
    const int cl = tid & 31;
    const int rw = tid >> 5;

    float acc[4][4];
#pragma unroll
    for (int u = 0; u < 4; u++)
#pragma unroll
        for (int v = 0; v < 4; v++) acc[u][v] = 0.0f;

    for (int k0 = 0; k0 < HID; k0 += 32) {
#pragma unroll
        for (int i = 0; i < 8; i++) {
            As[cl][rw + i * 8] = h[(m0 + rw + i * 8) * HID + k0 + cl];
            Bn[cl][rw + i * 8] = Wp[(n0 + rw + i * 8) * HID + k0 + cl];
        }
        __syncthreads();
        const int bbv = (tid >> 4) << 2;
        const int nnv = (tid & 15) << 2;
#pragma unroll
        for (int k = 0; k < 32; k++) {
            float4 a = *reinterpret_cast<const float4*>(&As[k][bbv]);
            float4 w = *reinterpret_cast<const float4*>(&Bn[k][nnv]);
            float av[4] = {a.x, a.y, a.z, a.w};
            float wv[4] = {w.x, w.y, w.z, w.w};
#pragma unroll
            for (int u = 0; u < 4; u++)
#pragma unroll
                for (int v = 0; v < 4; v++)
                    acc[u][v] += av[u] * wv[v];
        }
        __syncthreads();
    }

    const int bbv = (tid >> 4) << 2;
    const int nnv = (tid & 15) << 2;
#pragma unroll
    for (int u = 0; u < 4; u++)
#pragma unroll
        for (int v = 0; v < 4; v++)
            out[(m0 + bbv + u) * MOUT + n0 + nnv + v] = acc[u][v] + bp[n0 + nnv + v];
}

// ---------------- launch ----------------
extern "C" void kernel_launch(void* const* d_in, const int* in_sizes, int n_in,
                              void* d_out, int out_size) {
    (void)in_sizes; (void)n_in; (void)out_size;
    const float* x   = (const float*)d_in[0];
    const float* Wgx = (const float*)d_in[1];
    const float* bg  = (const float*)d_in[2];
    const float* Wgh = (const float*)d_in[3];
    const float* Wix = (const float*)d_in[4];
    const float* bi  = (const float*)d_in[5];
    const float* Wih = (const float*)d_in[6];
    const float* Wfx = (const float*)d_in[7];
    const float* bf  = (const float*)d_in[8];
    const float* Wfh = (const float*)d_in[9];
    const float* Wox = (const float*)d_in[10];
    const float* bo  = (const float*)d_in[11];
    const float* Woh = (const float*)d_in[12];
    const float* Wp  = (const float*)d_in[13];
    const float* bp  = (const float*)d_in[14];
    float* out = (float*)d_out;

    cudaFuncSetAttribute(lstm_step_mma, cudaFuncAttributeMaxDynamicSharedMemorySize, SMEM_DYN);

    init_state<<<(BATCH * HID + 255) / 256, 256>>>();
    split_x<<<(BATCH * SEQ * NIN + 255) / 256, 256>>>(x);
    pack_w<<<(GDIM * KTOT + 255) / 256, 256>>>(Wgh, Wih, Wfh, Woh, Wgx, Wix, Wfx, Wox);
    pack_b<<<(GDIM + 255) / 256, 256>>>(bg, bi, bf, bo);

    dim3 sgrid(BATCH / TM, GDIM / TN);   // (4, 32) = 128 CTAs
    for (int t = 0; t < SEQ; t++) {
        lstm_step_mma<<<sgrid, 256, SMEM_DYN>>>(t);
    }

    proj_kernel<<<dim3(BATCH / 64, MOUT / 64), 256>>>(Wp, bp, out);
}

// round 6
// speedup vs baseline: 4.6260x; 1.3252x over previous
#include <cuda_runtime.h>
#include <cuda_fp16.h>
#include <math.h>
#include <stdint.h>

#define BATCH 256
#define SEQ   256
#define NIN   512
#define HID   1024
#define MOUT  512
#define GDIM  4096            // 4*HID packed gate columns (p = 4j + gate)
#define KTOT  1536            // HID + NIN
#define KC    64              // K per chunk (64 fp16 = 128B rows)
#define NCHUNK (KTOT / KC)    // 24

#define TM 64
#define TN 128
// per-stage tiles: A_hi 8K | B_hi 16K | B_lo 16K
#define B_HI_OFF  8192
#define B_LO_OFF 24576
#define STAGE_BYTES 40960
#define SMEM_DYN (1024 + 2 * STAGE_BYTES)   // 1KB slack for 1024B tile alignment

#define LO_SCALE   2048.0f
#define INV_LO     4.8828125e-4f   // 1/2048

// ---------------- device scratch (static; no allocations) ----------------
__device__ __align__(256) float   g_c[2][BATCH * HID];
__device__ __align__(256) __half  g_h16[2][BATCH * HID];
__device__ __align__(256) float   g_hf[BATCH * HID];
__device__ __align__(256) __half  g_whi[GDIM * KTOT];
__device__ __align__(256) __half  g_wlo[GDIM * KTOT];   // (w - whi) * 2048
__device__ __align__(256) float   g_bpack[GDIM];
__device__ __align__(256) __half  g_x16[BATCH * SEQ * NIN];

// ---------------- helpers ----------------
__device__ __forceinline__ uint32_t smem_u32(const void* p) {
    uint32_t a;
    asm("{ .reg .u64 t; cvta.to.shared.u64 t, %1; cvt.u32.u64 %0, t; }" : "=r"(a) : "l"(p));
    return a;
}
__device__ __forceinline__ uint32_t swz128(uint32_t off) {
    return off ^ ((off >> 3) & 0x70);
}
__device__ __forceinline__ void cp16(uint32_t dst, const void* src) {
    asm volatile("cp.async.cg.shared.global [%0], [%1], 16;" :: "r"(dst), "l"(src) : "memory");
}
#define CP_COMMIT() asm volatile("cp.async.commit_group;" ::: "memory")
#define CP_WAIT(n)  asm volatile("cp.async.wait_group %0;" :: "n"(n) : "memory")

#define LDSM4(r, addr) \
    asm volatile("ldmatrix.sync.aligned.m8n8.x4.shared.b16 {%0,%1,%2,%3}, [%4];" \
        : "=r"((r)[0]), "=r"((r)[1]), "=r"((r)[2]), "=r"((r)[3]) : "r"(addr))

#define MMA16816(c, a, b) \
    asm volatile("mma.sync.aligned.m16n8k16.row.col.f32.f16.f16.f32 " \
        "{%0,%1,%2,%3}, {%4,%5,%6,%7}, {%8,%9}, {%0,%1,%2,%3};" \
        : "+f"((c)[0]), "+f"((c)[1]), "+f"((c)[2]), "+f"((c)[3]) \
        : "r"((a)[0]), "r"((a)[1]), "r"((a)[2]), "r"((a)[3]), \
          "r"((b)[0]), "r"((b)[1]))

__device__ __forceinline__ float sigmoidf_(float v) {
    return 1.0f / (1.0f + __expf(-v));
}

// ---------------- prologue kernels ----------------
__global__ void init_state() {
    int i = blockIdx.x * blockDim.x + threadIdx.x;
    if (i < BATCH * HID) {
        g_c[0][i] = 0.0f;
        g_h16[0][i] = __float2half(0.0f);
    }
}

__global__ void split_x(const float* __restrict__ x) {
    int i = blockIdx.x * blockDim.x + threadIdx.x;
    if (i < BATCH * SEQ * NIN) g_x16[i] = __float2half_rn(x[i]);
}

__global__ void pack_w(const float* __restrict__ Wgh, const float* __restrict__ Wih,
                       const float* __restrict__ Wfh, const float* __restrict__ Woh,
                       const float* __restrict__ Wgx, const float* __restrict__ Wix,
                       const float* __restrict__ Wfx, const float* __restrict__ Wox) {
    const float* Wh[4] = {Wgh, Wih, Wfh, Woh};
    const float* Wx[4] = {Wgx, Wix, Wfx, Wox};
    long i = (long)blockIdx.x * blockDim.x + threadIdx.x;
    if (i < (long)GDIM * KTOT) {
        int p = (int)(i / KTOT);
        int k = (int)(i % KTOT);
        int j = p >> 2, g = p & 3;
        float v = (k < HID) ? Wh[g][j * HID + k] : Wx[g][j * NIN + (k - HID)];
        __half hi = __float2half_rn(v);
        g_whi[i] = hi;
        g_wlo[i] = __float2half_rn((v - __half2float(hi)) * LO_SCALE);
    }
}

__global__ void pack_b(const float* __restrict__ bg, const float* __restrict__ bi,
                       const float* __restrict__ bf, const float* __restrict__ bo) {
    const float* bv[4] = {bg, bi, bf, bo};
    int p = blockIdx.x * blockDim.x + threadIdx.x;
    if (p < GDIM) g_bpack[p] = bv[p & 3][p >> 2];
}

// ---------------- mma.sync recurrent step ----------------
// Grid (4, 32); CTA tile 64 batch x 128 packed gate cols; K = 1536.
// Split-fp16 2-pass: z = Ah*Bh + (Ah*(Bl*2048)) * 2^-11  (fp32 accum, 2 reg sets)
__device__ __forceinline__ void issue_loads(
    int ck, int stage, int t, int tid, int m0, int p0,
    uint32_t tiles, const __half* h_in)
{
    const int k0 = ck * KC;
    const uint32_t sb = tiles + stage * STAGE_BYTES;
    // A: 64 rows x 8 16B-groups (hi only)
#pragma unroll
    for (int c = 0; c < 2; c++) {
        int id = tid + c * 256;          // 0..511
        int r = id >> 3, c8 = id & 7;
        uint32_t off = swz128((uint32_t)(r * 128 + c8 * 16));
        int row = m0 + r;
        const __half* gp;
        if (k0 < HID) {
            gp = &h_in[row * HID + k0 + c8 * 8];
        } else {
            gp = &g_x16[((size_t)row * SEQ + t) * NIN + (k0 - HID) + c8 * 8];
        }
        cp16(sb + off, gp);
    }
    // B: 128 rows x 8 16B-groups, hi + lo
#pragma unroll
    for (int c = 0; c < 4; c++) {
        int id = tid + c * 256;          // 0..1023
        int r = id >> 3, c8 = id & 7;
        uint32_t off = swz128((uint32_t)(r * 128 + c8 * 16));
        size_t wo = (size_t)(p0 + r) * KTOT + k0 + c8 * 8;
        cp16(sb + B_HI_OFF + off, &g_whi[wo]);
        cp16(sb + B_LO_OFF + off, &g_wlo[wo]);
    }
    CP_COMMIT();
}

__global__ __launch_bounds__(256, 1) void lstm_step_mma(int t) {
    extern __shared__ __align__(1024) char smem[];
    const uint32_t sbase = smem_u32(smem);
    const uint32_t tiles = (sbase + 1023u) & ~1023u;   // 1024B-aligned tile region

    const int tid = threadIdx.x;
    const int lane = tid & 31;
    const int wid = tid >> 5;
    const int wm = wid >> 2;    // 0..1  (M)
    const int wn = wid & 3;     // 0..3  (N)
    const int m0 = blockIdx.x * TM;
    const int p0 = blockIdx.y * TN;

    const int pin = t & 1, pout = pin ^ 1;
    const __half* h_in = g_h16[pin];
    const float* c_in = g_c[pin];
    float* c_out = g_c[pout];
    __half* h_out = g_h16[pout];

    // Per-lane unswizzled base offsets for ldmatrix addresses.
    const int mat = lane >> 3;
    uint32_t aBaseOff[2], bBaseOff[2];
#pragma unroll
    for (int mt = 0; mt < 2; mt++) {
        int rowA = wm * 32 + mt * 16 + (lane & 7) + (mat & 1) * 8;
        aBaseOff[mt] = (uint32_t)(rowA * 128 + ((lane >> 4) & 1) * 16);
    }
#pragma unroll
    for (int q = 0; q < 2; q++) {
        int rowB = wn * 32 + q * 16 + (mat >> 1) * 8 + (lane & 7);
        bBaseOff[q] = (uint32_t)(rowB * 128 + (mat & 1) * 16);
    }

    float accH[2][4][4], accL[2][4][4];
#pragma unroll
    for (int mt = 0; mt < 2; mt++)
#pragma unroll
        for (int nt = 0; nt < 4; nt++)
#pragma unroll
            for (int e = 0; e < 4; e++) { accH[mt][nt][e] = 0.0f; accL[mt][nt][e] = 0.0f; }

    issue_loads(0, 0, t, tid, m0, p0, tiles, h_in);

    for (int i = 0; i < NCHUNK; i++) {
        const int st = i & 1;
        if (i + 1 < NCHUNK) {
            issue_loads(i + 1, st ^ 1, t, tid, m0, p0, tiles, h_in);
            CP_WAIT(1);
        } else {
            CP_WAIT(0);
        }
        __syncthreads();   // chunk i visible to all warps

        const uint32_t sb = tiles + st * STAGE_BYTES;
#pragma unroll
        for (int ks = 0; ks < 4; ks++) {
            // A fragments loaded once, reused for both B passes.
            uint32_t a[2][4];
#pragma unroll
            for (int mt = 0; mt < 2; mt++)
                LDSM4(a[mt], sb + swz128(aBaseOff[mt] + ks * 32));

            uint32_t bh[4][2], bl[4][2];
#pragma unroll
            for (int q = 0; q < 2; q++) {
                uint32_t r4[4];
                LDSM4(r4, sb + B_HI_OFF + swz128(bBaseOff[q] + ks * 32));
                bh[2 * q][0] = r4[0]; bh[2 * q][1] = r4[1];
                bh[2 * q + 1][0] = r4[2]; bh[2 * q + 1][1] = r4[3];
            }
#pragma unroll
            for (int q = 0; q < 2; q++) {
                uint32_t r4[4];
                LDSM4(r4, sb + B_LO_OFF + swz128(bBaseOff[q] + ks * 32));
                bl[2 * q][0] = r4[0]; bl[2 * q][1] = r4[1];
                bl[2 * q + 1][0] = r4[2]; bl[2 * q + 1][1] = r4[3];
            }
#pragma unroll
            for (int mt = 0; mt < 2; mt++)
#pragma unroll
                for (int nt = 0; nt < 4; nt++) {
                    MMA16816(accH[mt][nt], a[mt], bh[nt]);
                    MMA16816(accL[mt][nt], a[mt], bl[nt]);
                }
        }
        __syncthreads();   // stage st free for overwrite next iteration
    }

    // ---- epilogue: combine hi/lo, exchange z via smem, gate math ----
    float* zs = (float*)(smem + (tiles - sbase));     // 64 x 132 fp32 = 33792 B
#pragma unroll
    for (int mt = 0; mt < 2; mt++)
#pragma unroll
        for (int nt = 0; nt < 4; nt++) {
            int r = wm * 32 + mt * 16 + (lane >> 2);
            int cc = wn * 32 + nt * 8 + (lane & 3) * 2;
            zs[r * 132 + cc]           = accH[mt][nt][0] + accL[mt][nt][0] * INV_LO;
            zs[r * 132 + cc + 1]       = accH[mt][nt][1] + accL[mt][nt][1] * INV_LO;
            zs[(r + 8) * 132 + cc]     = accH[mt][nt][2] + accL[mt][nt][2] * INV_LO;
            zs[(r + 8) * 132 + cc + 1] = accH[mt][nt][3] + accL[mt][nt][3] * INV_LO;
        }
    __syncthreads();

#pragma unroll
    for (int e = 0; e < 8; e++) {
        int idx = tid + e * 256;          // 0..2047
        int r = idx >> 5;                 // 0..63
        int jj = idx & 31;                // 0..31
        int b = m0 + r;
        int j = (p0 >> 2) + jj;
        float4 z = *reinterpret_cast<const float4*>(&zs[r * 132 + jj * 4]);
        float4 bb = *reinterpret_cast<const float4*>(&g_bpack[p0 + jj * 4]);
        float zg = z.x + bb.x;
        float zi = z.y + bb.y;
        float zf = z.z + bb.z;
        float zo = z.w + bb.w;
        float cp = c_in[b * HID + j];
        float cn = tanhf(zg) * sigmoidf_(zi) + cp * sigmoidf_(zf);
        float hn = tanhf(cn) * sigmoidf_(zo);
        c_out[b * HID + j] = cn;
        g_hf[b * HID + j] = hn;
        h_out[b * HID + j] = __float2half_rn(hn);
    }
}

// ---------------- final projection (SIMT fp32) ----------------
__global__ __launch_bounds__(256) void proj_kernel(
    const float* __restrict__ Wp, const float* __restrict__ bp,
    float* __restrict__ out)
{
    const float* h = g_hf;
    __shared__ __align__(16) float As[32][68];
    __shared__ __align__(16) float Bn[32][68];

    const int tid = threadIdx.x;
    const int m0 = blockIdx.x * 64;
    const int n0 = blockIdx.y * 64;
    const int cl = tid & 31;
    const int rw = tid >> 5;

    float acc[4][4];
#pragma unroll
    for (int u = 0; u < 4; u++)
#pragma unroll
        for (int v = 0; v < 4; v++) acc[u][v] = 0.0f;

    for (int k0 = 0; k0 < HID; k0 += 32) {
#pragma unroll
        for (int i = 0; i < 8; i++) {
            As[cl][rw + i * 8] = h[(m0 + rw + i * 8) * HID + k0 + cl];
            Bn[cl][rw + i * 8] = Wp[(n0 + rw + i * 8) * HID + k0 + cl];
        }
        __syncthreads();
        const int bbv = (tid >> 4) << 2;
        const int nnv = (tid & 15) << 2;
#pragma unroll
        for (int k = 0; k < 32; k++) {
            float4 a = *reinterpret_cast<const float4*>(&As[k][bbv]);
            float4 w = *reinterpret_cast<const float4*>(&Bn[k][nnv]);
            float av[4] = {a.x, a.y, a.z, a.w};
            float wv[4] = {w.x, w.y, w.z, w.w};
#pragma unroll
            for (int u = 0; u < 4; u++)
#pragma unroll
                for (int v = 0; v < 4; v++)
                    acc[u][v] += av[u] * wv[v];
        }
        __syncthreads();
    }

    const int bbv = (tid >> 4) << 2;
    const int nnv = (tid & 15) << 2;
#pragma unroll
    for (int u = 0; u < 4; u++)
#pragma unroll
        for (int v = 0; v < 4; v++)
            out[(m0 + bbv + u) * MOUT + n0 + nnv + v] = acc[u][v] + bp[n0 + nnv + v];
}

// ---------------- launch ----------------
extern "C" void kernel_launch(void* const* d_in, const int* in_sizes, int n_in,
                              void* d_out, int out_size) {
    (void)in_sizes; (void)n_in; (void)out_size;
    const float* x   = (const float*)d_in[0];
    const float* Wgx = (const float*)d_in[1];
    const float* bg  = (const float*)d_in[2];
    const float* Wgh = (const float*)d_in[3];
    const float* Wix = (const float*)d_in[4];
    const float* bi  = (const float*)d_in[5];
    const float* Wih = (const float*)d_in[6];
    const float* Wfx = (const float*)d_in[7];
    const float* bf  = (const float*)d_in[8];
    const float* Wfh = (const float*)d_in[9];
    const float* Wox = (const float*)d_in[10];
    const float* bo  = (const float*)d_in[11];
    const float* Woh = (const float*)d_in[12];
    const float* Wp  = (const float*)d_in[13];
    const float* bp  = (const float*)d_in[14];
    float* out = (float*)d_out;

    cudaFuncSetAttribute(lstm_step_mma, cudaFuncAttributeMaxDynamicSharedMemorySize, SMEM_DYN);

    init_state<<<(BATCH * HID + 255) / 256, 256>>>();
    split_x<<<(BATCH * SEQ * NIN + 255) / 256, 256>>>(x);
    pack_w<<<(GDIM * KTOT + 255) / 256, 256>>>(Wgh, Wih, Wfh, Woh, Wgx, Wix, Wfx, Wox);
    pack_b<<<(GDIM + 255) / 256, 256>>>(bg, bi, bf, bo);

    dim3 sgrid(BATCH / TM, GDIM / TN);   // (4, 32) = 128 CTAs
    for (int t = 0; t < SEQ; t++) {
        lstm_step_mma<<<sgrid, 256, SMEM_DYN>>>(t);
    }

    proj_kernel<<<dim3(BATCH / 64, MOUT / 64), 256>>>(Wp, bp, out);
}